// round 16
// baseline (speedup 1.0000x reference)
#include <cuda_runtime.h>
#include <cuda_fp16.h>
#include <cstdint>

#define BATCH 32
#define VLEN  4096
#define HDIM  1024

// ---------------- device scratch ----------------
__device__ float g_qb[BATCH * HDIM];
__device__ float g_score[BATCH * VLEN];
__device__ __align__(16) __half g_wk[HDIM * HDIM];
__device__ __align__(16) __half g_key16[(size_t)BATCH * VLEN * HDIM];
__device__ float g_ctx_part[16 * BATCH * HDIM];

// persistent-kernel scheduling state (zeroed by setup_kernel each launch)
__device__ int g_next;
__device__ int g_done_score[BATCH];   // 64 tiles per b
__device__ int g_soft_flag[BATCH];
__device__ int g_ctx_done[BATCH];     // 16 partial jobs per b

#define N_SCORE   2048
#define J_SOFT    (N_SCORE)            // 2048..2079
#define J_CTX     (J_SOFT + BATCH)     // 2080..2591
#define J_RED     (J_CTX + BATCH * 16) // 2592..2623
#define N_JOBS    (J_RED + BATCH)      // 2624
#define GRID_P    444                  // 148 SMs x 3 CTAs

// ---------------- helpers ----------------
__device__ __forceinline__ uint32_t smem_u32(const void* p) {
    uint32_t a;
    asm("{ .reg .u64 t; cvta.to.shared.u64 t, %1; cvt.u32.u64 %0, t; }" : "=r"(a) : "l"(p));
    return a;
}
__device__ __forceinline__ void cp16(uint32_t saddr, const void* g) {
    asm volatile("cp.async.cg.shared.global [%0], [%1], 16;" :: "r"(saddr), "l"(g) : "memory");
}
#define CP_COMMIT()  asm volatile("cp.async.commit_group;" ::: "memory")
#define CP_WAIT(N)   asm volatile("cp.async.wait_group %0;" :: "n"(N) : "memory")

__device__ __forceinline__ void ldsm4(uint32_t* r, uint32_t addr) {
    asm volatile("ldmatrix.sync.aligned.m8n8.x4.shared.b16 {%0,%1,%2,%3}, [%4];"
                 : "=r"(r[0]), "=r"(r[1]), "=r"(r[2]), "=r"(r[3]) : "r"(addr));
}
__device__ __forceinline__ void mma_f16(float* d, const uint32_t* a, uint32_t b0, uint32_t b1) {
    asm volatile("mma.sync.aligned.m16n8k16.row.col.f32.f16.f16.f32 "
                 "{%0,%1,%2,%3}, {%4,%5,%6,%7}, {%8,%9}, {%0,%1,%2,%3};"
                 : "+f"(d[0]), "+f"(d[1]), "+f"(d[2]), "+f"(d[3])
                 : "r"(a[0]), "r"(a[1]), "r"(a[2]), "r"(a[3]), "r"(b0), "r"(b1));
}
__device__ __forceinline__ uint32_t pkh(float a, float b) {
    __half2 h = __floats2half2_rn(a, b);
    return *reinterpret_cast<uint32_t*>(&h);
}
__device__ __forceinline__ float ftanh(float x) {
    float e = __expf(2.0f * x);
    return 1.0f - __fdividef(2.0f, e + 1.0f);
}

// ---------------- SMEM layout (bytes) ----------------
// M-tile 64, N-tile 128, K-chunk 32 fp16 (64 B/row), pitch 80 B.
// per stage: [A 64*80 = 5120][B 128*80 = 10240] = 15360; 4 stages (pow2 ->
// compile-time stage indices after 4x unroll).
#define PITCH    80
#define OFF_B    5120
#define BUFSZ    15360
#define NSTAGE   4
#define SM_QB    (NSTAGE * BUFSZ)     // 61440
#define SM_WS    (SM_QB + 4096)       // 65536
#define SM_RED   (SM_WS + 4096)       // 69632
#define SM_TOTAL (SM_RED + 1024)      // 70656 (x3 CTAs = 212 KB/SM)

// ---------------------------------------------------------------------------
// setup: blocks [0,1024) Wk->fp16; [1024,5120) qb; block 5120 zeroes counters
// ---------------------------------------------------------------------------
__global__ void setup_kernel(const float* __restrict__ query,
                             const float* __restrict__ Wq,
                             const float* __restrict__ bias,
                             const float* __restrict__ Wk) {
    if (blockIdx.x == 5120) {
        if (threadIdx.x < BATCH) {
            g_done_score[threadIdx.x] = 0;
            g_soft_flag[threadIdx.x]  = 0;
            g_ctx_done[threadIdx.x]   = 0;
        }
        if (threadIdx.x == 0) g_next = 0;
    } else if (blockIdx.x < 1024) {
        int i = (blockIdx.x * 256 + threadIdx.x) * 4;
        float4 w = *reinterpret_cast<const float4*>(Wk + i);
        *reinterpret_cast<uint2*>(g_wk + i) = make_uint2(pkh(w.x, w.y), pkh(w.z, w.w));
    } else {
        int w    = (((int)blockIdx.x - 1024) * 256 + (int)threadIdx.x) >> 5;
        int lane = threadIdx.x & 31;
        int b = w / HDIM;
        int o = w % HDIM;
        const float* wrow = Wq + (size_t)o * HDIM;
        const float* qrow = query + (size_t)b * HDIM;
        float s = 0.0f;
#pragma unroll 8
        for (int h = lane; h < HDIM; h += 32) s += wrow[h] * qrow[h];
#pragma unroll
        for (int off = 16; off; off >>= 1) s += __shfl_xor_sync(0xffffffffu, s, off);
        if (lane == 0) g_qb[w] = s + bias[o];
    }
}

// ---------------------------------------------------------------------------
// Persistent fused kernel: 444 CTAs pull jobs off a global counter.
//  [0,2048)      score tiles (b = j>>6, v0 = (j&63)*64)
//  [2048,2080)   softmax per b (spin: 64 score tiles of b done)
//  [2080,2592)   context partials (b = k>>4, vs = k&15; spin: softmax b done)
//  [2592,2624)   context reduce per b (spin: 16 partials of b done)
// ---------------------------------------------------------------------------
__global__ void __launch_bounds__(256, 3)
fused_kernel(const float* __restrict__ key, const float* __restrict__ Ws,
             const float* __restrict__ value,
             float* __restrict__ attn_out, float* __restrict__ ctx_out) {
    extern __shared__ __align__(16) char smem[];
    __shared__ int s_job;
    __shared__ float red[256];
    const uint32_t sb = smem_u32(smem);
    const int tid  = threadIdx.x;
    const int lane = tid & 31;
    const int wid  = tid >> 5;

    for (;;) {
        __syncthreads();                         // quiesce smem before reuse
        if (tid == 0) s_job = atomicAdd(&g_next, 1);
        __syncthreads();
        const int js = s_job;
        if (js >= N_JOBS) return;

        if (js < N_SCORE) {
            // ================= score tile =================
            const int b  = js >> 6;
            const int v0 = (js & 63) * 64;
            const int wy = wid >> 2, wx = wid & 3;
            const size_t kbase = ((size_t)b * VLEN + v0) * HDIM;

            // convert this tile's 64x1024 key block to fp16 (tile-private;
            // __syncthreads below is a CTA-scope fence -> own LDG sees it)
            {
                const float* kf = key + kbase;
                __half* kh = g_key16 + kbase;
#pragma unroll 4
                for (int it = 0; it < 32; it++) {
                    const int e = (tid + it * 256) * 8;
                    const float4 a = *reinterpret_cast<const float4*>(kf + e);
                    const float4 c = *reinterpret_cast<const float4*>(kf + e + 4);
                    __stcg(reinterpret_cast<uint4*>(kh + e),
                           make_uint4(pkh(a.x, a.y), pkh(a.z, a.w), pkh(c.x, c.y), pkh(c.z, c.w)));
                }
            }

            float* qbs = reinterpret_cast<float*>(smem + SM_QB);
            float* wss = reinterpret_cast<float*>(smem + SM_WS);
#pragma unroll
            for (int i = 0; i < 4; i++) {
                qbs[tid + i * 256] = g_qb[b * HDIM + tid + i * 256];
                wss[tid + i * 256] = Ws[tid + i * 256];
            }
            __syncthreads();

            const __half* keyb = g_key16 + kbase;
            const int arow = tid >> 2, aseg = tid & 3;
            const int brow = tid >> 1, bseg = (tid & 1) * 2;

            const uint32_t aoff  = (uint32_t)((lane & 15) * PITCH + (lane >> 4) * 16);
            const uint32_t Abase = sb + (uint32_t)(wy * 32 * PITCH) + aoff;
            const uint32_t Bbase = sb + OFF_B + (uint32_t)(wx * 32 * PITCH) + aoff;
            const uint32_t sa_a  = (uint32_t)(arow * PITCH + aseg * 16);
            const uint32_t sa_b0 = (uint32_t)(OFF_B + brow * PITCH + bseg * 16);
            const __half* kap = keyb + (size_t)arow * HDIM + aseg * 8;
            const __half* wbp = g_wk + (size_t)brow * HDIM + bseg * 8;

            float d[2][4][4];
#pragma unroll
            for (int mt = 0; mt < 2; mt++)
#pragma unroll
                for (int j = 0; j < 4; j++)
#pragma unroll
                    for (int q = 0; q < 4; q++) d[mt][j][q] = 0.0f;
            float part[4] = {0.f, 0.f, 0.f, 0.f};

            auto issue_b = [&](int n, int s) {
                const int oh = (n >> 5) * (128 * HDIM) + (n & 31) * 32;
                const uint32_t bb = sb + (uint32_t)s * BUFSZ;
                cp16(bb + sa_b0, wbp + oh);
                cp16(bb + sa_b0 + 16, wbp + oh + 8);
                CP_COMMIT();
            };
            auto a_addr = [&](int n) { return kap + (n & 31) * 32; };

            auto compute_chunk = [&](int su) {
                const uint32_t abuf = Abase + (uint32_t)su * BUFSZ;
                const uint32_t bbuf = Bbase + (uint32_t)su * BUFSZ;
#pragma unroll
                for (int ks = 0; ks < 2; ks++) {
                    uint32_t Bh[2][4];
#pragma unroll
                    for (int jj = 0; jj < 2; jj++)
                        ldsm4(Bh[jj], bbuf + jj * (16 * PITCH) + ks * 32);
                    uint32_t Ah[2][4];
#pragma unroll
                    for (int mt = 0; mt < 2; mt++)
                        ldsm4(Ah[mt], abuf + mt * (16 * PITCH) + ks * 32);
#pragma unroll
                    for (int mt = 0; mt < 2; mt++)
#pragma unroll
                        for (int jj = 0; jj < 2; jj++)
#pragma unroll
                            for (int h = 0; h < 2; h++)
                                mma_f16(d[mt][jj * 2 + h], Ah[mt], Bh[jj][h], Bh[jj][2 + h]);
                }
            };

            auto do_epilogue = [&](int pass) {
                const int o0 = pass * 128;
                const int cb = o0 + wx * 32 + (lane & 3) * 2;
#pragma unroll
                for (int mt = 0; mt < 2; mt++) {
#pragma unroll
                    for (int j = 0; j < 4; j++) {
                        const int o = cb + j * 8;
                        const float w0 = wss[o], w1 = wss[o + 1];
                        const float q0 = qbs[o], q1 = qbs[o + 1];
                        part[mt * 2 + 0] += w0 * ftanh(d[mt][j][0] + q0) + w1 * ftanh(d[mt][j][1] + q1);
                        part[mt * 2 + 1] += w0 * ftanh(d[mt][j][2] + q0) + w1 * ftanh(d[mt][j][3] + q1);
                        d[mt][j][0] = 0.0f; d[mt][j][1] = 0.0f;
                        d[mt][j][2] = 0.0f; d[mt][j][3] = 0.0f;
                    }
                }
            };

            // ---- pipeline prologue ----
            uint4 a0    = *reinterpret_cast<const uint4*>(a_addr(0));
            uint4 apend = *reinterpret_cast<const uint4*>(a_addr(1));
            issue_b(0, 0);
            issue_b(1, 1);
            *reinterpret_cast<uint4*>(smem + sa_a) = a0;   // A chunk 0 -> stage 0

            // ---- hot loop: gc = 0..251, stage = gc & 3 (compile-time via unroll)
            for (int o = 0; o < 63; o++) {
#pragma unroll
                for (int u = 0; u < 4; u++) {
                    const int gc = o * 4 + u;
                    CP_WAIT(1);
                    __syncthreads();
                    // STS pending A (chunk gc+1) into stage (u+1)&3
                    *reinterpret_cast<uint4*>(smem + (size_t)((u + 1) & 3) * BUFSZ + sa_a) = apend;
                    // fetch A gc+2; issue B gc+2 into stage (u+2)&3
                    apend = *reinterpret_cast<const uint4*>(a_addr(gc + 2));
                    issue_b(gc + 2, (u + 2) & 3);
                    compute_chunk(u);
                }
                if ((o & 7) == 7) do_epilogue(o >> 3);   // gc = 31,63,...,223
            }
            // ---- tail: gc = 252..255 ----
            CP_WAIT(1); __syncthreads();                                   // gc=252
            *reinterpret_cast<uint4*>(smem + (size_t)1 * BUFSZ + sa_a) = apend;
            apend = *reinterpret_cast<const uint4*>(a_addr(254));
            issue_b(254, 2);
            compute_chunk(0);
            CP_WAIT(1); __syncthreads();                                   // gc=253
            *reinterpret_cast<uint4*>(smem + (size_t)2 * BUFSZ + sa_a) = apend;
            apend = *reinterpret_cast<const uint4*>(a_addr(255));
            issue_b(255, 3);
            compute_chunk(1);
            CP_WAIT(1); __syncthreads();                                   // gc=254
            *reinterpret_cast<uint4*>(smem + (size_t)3 * BUFSZ + sa_a) = apend;
            compute_chunk(2);
            CP_WAIT(0); __syncthreads();                                   // gc=255
            compute_chunk(3);
            do_epilogue(7);

            // ---- cross-thread reduction ----
#pragma unroll
            for (int i = 0; i < 4; i++) {
                part[i] += __shfl_xor_sync(0xffffffffu, part[i], 1);
                part[i] += __shfl_xor_sync(0xffffffffu, part[i], 2);
            }
            float* rd = reinterpret_cast<float*>(smem + SM_RED);
            if ((lane & 3) == 0) {
                const int r0 = wy * 32 + (lane >> 2);
#pragma unroll
                for (int mt = 0; mt < 2; mt++) {
                    rd[wx * 64 + r0 + mt * 16]     = part[mt * 2 + 0];
                    rd[wx * 64 + r0 + mt * 16 + 8] = part[mt * 2 + 1];
                }
            }
            __syncthreads();
            if (tid < 64) {
                const float s = rd[tid] + rd[64 + tid] + rd[128 + tid] + rd[192 + tid];
                g_score[b * VLEN + v0 + tid] = s;
            }
            __threadfence();
            __syncthreads();
            if (tid == 0) atomicAdd(&g_done_score[b], 1);

        } else if (js < J_CTX) {
            // ================= softmax for batch b =================
            const int b = js - J_SOFT;
            if (tid == 0) {
                while (atomicAdd(&g_done_score[b], 0) < 64) __nanosleep(200);
            }
            __syncthreads();
            __threadfence();

            const float* s = g_score + b * VLEN;
            float local[16];
            float mx = -1e30f;
#pragma unroll
            for (int i = 0; i < 16; i++) {
                local[i] = s[tid + i * 256];
                mx = fmaxf(mx, local[i]);
            }
            red[tid] = mx;
            __syncthreads();
            for (int o = 128; o; o >>= 1) {
                if (tid < o) red[tid] = fmaxf(red[tid], red[tid + o]);
                __syncthreads();
            }
            mx = red[0];
            __syncthreads();
            float sum = 0.0f;
#pragma unroll
            for (int i = 0; i < 16; i++) {
                local[i] = expf(local[i] - mx);
                sum += local[i];
            }
            red[tid] = sum;
            __syncthreads();
            for (int o = 128; o; o >>= 1) {
                if (tid < o) red[tid] += red[tid + o];
                __syncthreads();
            }
            const float inv = 1.0f / red[0];
#pragma unroll
            for (int i = 0; i < 16; i++) attn_out[b * VLEN + tid + i * 256] = local[i] * inv;

            __threadfence();
            __syncthreads();
            if (tid == 0) atomicExch(&g_soft_flag[b], 1);

        } else if (js < J_RED) {
            // ================= context partial (b, vs) =================
            const int k  = js - J_CTX;
            const int b  = k >> 4;
            const int vs = k & 15;
            if (tid == 0) {
                while (atomicAdd(&g_soft_flag[b], 0) == 0) __nanosleep(200);
            }
            __syncthreads();
            __threadfence();

            float* a_s = reinterpret_cast<float*>(smem);
            const int v0 = vs * 256;
            a_s[tid] = attn_out[b * VLEN + v0 + tid];
            __syncthreads();

            const int h = tid * 4;
            const float* vp = value + ((size_t)b * VLEN + v0) * HDIM + h;
            float ax = 0.f, ay = 0.f, az = 0.f, aw = 0.f;
            for (int v = 0; v < 256; v += 8) {
#pragma unroll
                for (int j = 0; j < 8; j++) {
                    const float4 x = *reinterpret_cast<const float4*>(vp + (size_t)(v + j) * HDIM);
                    const float a = a_s[v + j];
                    ax += a * x.x; ay += a * x.y; az += a * x.z; aw += a * x.w;
                }
            }
            *reinterpret_cast<float4*>(g_ctx_part + ((size_t)vs * BATCH + b) * HDIM + h) =
                make_float4(ax, ay, az, aw);
            __threadfence();
            __syncthreads();
            if (tid == 0) atomicAdd(&g_ctx_done[b], 1);

        } else {
            // ================= context reduce for batch b =================
            const int b = js - J_RED;
            if (tid == 0) {
                while (atomicAdd(&g_ctx_done[b], 0) < 16) __nanosleep(200);
            }
            __syncthreads();
            __threadfence();
#pragma unroll
            for (int r = 0; r < 4; r++) {
                const int h = tid + r * 256;
                float s = 0.0f;
#pragma unroll
                for (int vs = 0; vs < 16; vs++)
                    s += g_ctx_part[(size_t)vs * BATCH * HDIM + b * HDIM + h];
                ctx_out[b * HDIM + h] = s;
            }
        }
    }
}

// ---------------------------------------------------------------------------
// Launch. Inputs: query, key, value, Wq, Wk, bias, Ws, bs.
// Output: context (32*1024) then attn (32*4096).
// ---------------------------------------------------------------------------
extern "C" void kernel_launch(void* const* d_in, const int* in_sizes, int n_in,
                              void* d_out, int out_size) {
    const float* query = (const float*)d_in[0];
    const float* key   = (const float*)d_in[1];
    const float* value = (const float*)d_in[2];
    const float* Wq    = (const float*)d_in[3];
    const float* Wk    = (const float*)d_in[4];
    const float* bias  = (const float*)d_in[5];
    const float* Ws    = (const float*)d_in[6];

    float* out  = (float*)d_out;
    float* ctx  = out;                    // (B, 1, H)
    float* attn = out + BATCH * HDIM;     // (B, V)

    cudaFuncSetAttribute(fused_kernel, cudaFuncAttributeMaxDynamicSharedMemorySize, SM_TOTAL);

    setup_kernel<<<5121, 256>>>(query, Wq, bias, Wk);
    fused_kernel<<<GRID_P, 256, SM_TOTAL>>>(key, Ws, value, attn, ctx);
}

// round 17
// speedup vs baseline: 1.0152x; 1.0152x over previous
#include <cuda_runtime.h>
#include <cuda_fp16.h>
#include <cstdint>

#define BATCH 32
#define VLEN  4096
#define HDIM  1024

// ---------------- device scratch ----------------
__device__ float g_qb[BATCH * HDIM];
__device__ float g_score[BATCH * VLEN];
__device__ __align__(16) __half g_wk[HDIM * HDIM];
__device__ __align__(16) __half g_key16[(size_t)BATCH * VLEN * HDIM];
__device__ float g_ctx_part[16 * BATCH * HDIM];

// persistent-kernel scheduling state (zeroed by init_kernel each launch)
__device__ int g_next;
__device__ int g_wk_done;             // 64 conversion jobs
__device__ int g_qb_done[BATCH];      // 8 qb jobs per b
__device__ int g_done_score[BATCH];   // 64 tiles per b
__device__ int g_soft_flag[BATCH];
__device__ int g_ctx_done[BATCH];     // 16 partial jobs per b

// job queue layout
#define J_WK      0                     // [0,64)      Wk -> fp16
#define J_QB      64                    // [64,320)    qb (b = k>>3, oc = k&7)
#define J_SCORE   320                   // [320,2368)  score tiles
#define J_SOFT    2368                  // [2368,2400) softmax per b
#define J_CTX     2400                  // [2400,2912) context partials
#define J_RED     2912                  // [2912,2944) context reduce per b
#define N_JOBS    2944
#define GRID_P    444                   // 148 SMs x 3 CTAs

// ---------------- helpers ----------------
__device__ __forceinline__ uint32_t smem_u32(const void* p) {
    uint32_t a;
    asm("{ .reg .u64 t; cvta.to.shared.u64 t, %1; cvt.u32.u64 %0, t; }" : "=r"(a) : "l"(p));
    return a;
}
__device__ __forceinline__ void cp16(uint32_t saddr, const void* g) {
    asm volatile("cp.async.cg.shared.global [%0], [%1], 16;" :: "r"(saddr), "l"(g) : "memory");
}
#define CP_COMMIT()  asm volatile("cp.async.commit_group;" ::: "memory")
#define CP_WAIT(N)   asm volatile("cp.async.wait_group %0;" :: "n"(N) : "memory")

__device__ __forceinline__ void ldsm4(uint32_t* r, uint32_t addr) {
    asm volatile("ldmatrix.sync.aligned.m8n8.x4.shared.b16 {%0,%1,%2,%3}, [%4];"
                 : "=r"(r[0]), "=r"(r[1]), "=r"(r[2]), "=r"(r[3]) : "r"(addr));
}
__device__ __forceinline__ void mma_f16(float* d, const uint32_t* a, uint32_t b0, uint32_t b1) {
    asm volatile("mma.sync.aligned.m16n8k16.row.col.f32.f16.f16.f32 "
                 "{%0,%1,%2,%3}, {%4,%5,%6,%7}, {%8,%9}, {%0,%1,%2,%3};"
                 : "+f"(d[0]), "+f"(d[1]), "+f"(d[2]), "+f"(d[3])
                 : "r"(a[0]), "r"(a[1]), "r"(a[2]), "r"(a[3]), "r"(b0), "r"(b1));
}
__device__ __forceinline__ uint32_t pkh(float a, float b) {
    __half2 h = __floats2half2_rn(a, b);
    return *reinterpret_cast<uint32_t*>(&h);
}
__device__ __forceinline__ float ftanh(float x) {
    float e = __expf(2.0f * x);
    return 1.0f - __fdividef(2.0f, e + 1.0f);
}

// ---------------- SMEM layout (bytes) ---- R15-proven config ----
#define PITCH    80
#define OFF_B    5120
#define BUFSZ    15360
#define NSTAGE   3
#define SM_QB    (NSTAGE * BUFSZ)     // 46080
#define SM_WS    (SM_QB + 4096)
#define SM_RED   (SM_WS + 4096)
#define SM_TOTAL (SM_RED + 1024)      // 55296 (x3 CTAs = 166 KB/SM)

// ---------------------------------------------------------------------------
// init: one block zeroes all scheduler state (fast; graph-capturable)
// ---------------------------------------------------------------------------
__global__ void init_kernel() {
    const int t = threadIdx.x;
    if (t < BATCH) {
        g_qb_done[t]    = 0;
        g_done_score[t] = 0;
        g_soft_flag[t]  = 0;
        g_ctx_done[t]   = 0;
    }
    if (t == 0) { g_next = 0; g_wk_done = 0; }
}

// ---------------------------------------------------------------------------
// Persistent fused kernel: 444 CTAs pull jobs off a global counter.
//  [0,64)        Wk->fp16 conversion slices
//  [64,320)      qb chunks: b = k>>3, o in [ (k&7)*128, +128 )
//  [320,2368)    score tiles (spin: wk done + qb[b] done) — R15 body verbatim
//  [2368,2400)   softmax per b (spin: 64 score tiles of b)
//  [2400,2912)   context partials (spin: softmax b)
//  [2912,2944)   context reduce per b (spin: 16 partials of b)
// ---------------------------------------------------------------------------
__global__ void __launch_bounds__(256, 3)
fused_kernel(const float* __restrict__ key, const float* __restrict__ Ws,
             const float* __restrict__ value,
             const float* __restrict__ query, const float* __restrict__ Wq,
             const float* __restrict__ bias, const float* __restrict__ Wk,
             float* __restrict__ attn_out, float* __restrict__ ctx_out) {
    extern __shared__ __align__(16) char smem[];
    __shared__ int s_job;
    __shared__ float red[256];
    const uint32_t sb = smem_u32(smem);
    const int tid  = threadIdx.x;
    const int lane = tid & 31;
    const int wid  = tid >> 5;

    for (;;) {
        __syncthreads();                         // quiesce smem before reuse
        if (tid == 0) s_job = atomicAdd(&g_next, 1);
        __syncthreads();
        const int js = s_job;
        if (js >= N_JOBS) return;

        if (js < J_QB) {
            // ================= Wk conversion slice =================
            const int base = js * 16384;         // elements
#pragma unroll
            for (int it = 0; it < 16; it++) {
                const int i = base + (tid + it * 256) * 4;
                float4 w = *reinterpret_cast<const float4*>(Wk + i);
                *reinterpret_cast<uint2*>(g_wk + i) =
                    make_uint2(pkh(w.x, w.y), pkh(w.z, w.w));
            }
            __threadfence();
            __syncthreads();
            if (tid == 0) atomicAdd(&g_wk_done, 1);

        } else if (js < J_SCORE) {
            // ================= qb chunk: 128 outputs of batch b =================
            const int k  = js - J_QB;
            const int b  = k >> 3;
            const int o0 = (k & 7) * 128;
            const float* qrow = query + (size_t)b * HDIM;
            // each warp handles 16 rows, warp-collective dot
            for (int r = 0; r < 16; r++) {
                const int o = o0 + wid * 16 + r;
                const float* wrow = Wq + (size_t)o * HDIM;
                float s = 0.0f;
#pragma unroll 8
                for (int h = lane; h < HDIM; h += 32) s += wrow[h] * qrow[h];
#pragma unroll
                for (int off = 16; off; off >>= 1) s += __shfl_xor_sync(0xffffffffu, s, off);
                if (lane == 0) g_qb[b * HDIM + o] = s + bias[o];
            }
            __threadfence();
            __syncthreads();
            if (tid == 0) atomicAdd(&g_qb_done[b], 1);

        } else if (js < J_SOFT) {
            // ================= score tile (R15 body) =================
            const int js2 = js - J_SCORE;
            const int b  = js2 >> 6;
            const int v0 = (js2 & 63) * 64;
            const int wy = wid >> 2, wx = wid & 3;
            const size_t kbase = ((size_t)b * VLEN + v0) * HDIM;

            // wait for Wk conversion + this b's qb
            if (tid == 0) {
                while (atomicAdd(&g_wk_done, 0) < 64 ||
                       atomicAdd(&g_qb_done[b], 0) < 8) __nanosleep(100);
            }
            __syncthreads();
            __threadfence();

            // convert this tile's 64x1024 key block to fp16
            {
                const float* kf = key + kbase;
                __half* kh = g_key16 + kbase;
#pragma unroll 4
                for (int it = 0; it < 32; it++) {
                    const int e = (tid + it * 256) * 8;
                    const float4 a = *reinterpret_cast<const float4*>(kf + e);
                    const float4 c = *reinterpret_cast<const float4*>(kf + e + 4);
                    __stcg(reinterpret_cast<uint4*>(kh + e),
                           make_uint4(pkh(a.x, a.y), pkh(a.z, a.w), pkh(c.x, c.y), pkh(c.z, c.w)));
                }
                __threadfence();
            }

            float* qbs = reinterpret_cast<float*>(smem + SM_QB);
            float* wss = reinterpret_cast<float*>(smem + SM_WS);
#pragma unroll
            for (int i = 0; i < 4; i++) {
                qbs[tid + i * 256] = g_qb[b * HDIM + tid + i * 256];
                wss[tid + i * 256] = Ws[tid + i * 256];
            }
            __syncthreads();

            const __half* keyb = g_key16 + kbase;
            const int arow = tid >> 2, aseg = tid & 3;
            const int brow = tid >> 1, bseg = (tid & 1) * 2;

            const uint32_t aoff  = (uint32_t)((lane & 15) * PITCH + (lane >> 4) * 16);
            const uint32_t Abase = sb + (uint32_t)(wy * 32 * PITCH) + aoff;
            const uint32_t Bbase = sb + OFF_B + (uint32_t)(wx * 32 * PITCH) + aoff;
            const uint32_t sa_a  = (uint32_t)(arow * PITCH + aseg * 16);
            const uint32_t sa_b0 = (uint32_t)(OFF_B + brow * PITCH + bseg * 16);
            const __half* kap = keyb + (size_t)arow * HDIM + aseg * 8;
            const __half* wbp = g_wk + (size_t)brow * HDIM + bseg * 8;

            float d[2][4][4];
#pragma unroll
            for (int mt = 0; mt < 2; mt++)
#pragma unroll
                for (int j = 0; j < 4; j++)
#pragma unroll
                    for (int q = 0; q < 4; q++) d[mt][j][q] = 0.0f;
            float part[4] = {0.f, 0.f, 0.f, 0.f};

            auto issue_b = [&](int n, int s) {
                const int oh = (n >> 5) * (128 * HDIM) + (n & 31) * 32;
                const uint32_t bb = sb + (uint32_t)s * BUFSZ;
                cp16(bb + sa_b0, wbp + oh);
                cp16(bb + sa_b0 + 16, wbp + oh + 8);
                CP_COMMIT();
            };
            auto a_addr = [&](int n) { return kap + (n & 31) * 32; };

            uint4 a0    = *reinterpret_cast<const uint4*>(a_addr(0));
            uint4 apend = *reinterpret_cast<const uint4*>(a_addr(1));
            issue_b(0, 0);
            issue_b(1, 1);
            *reinterpret_cast<uint4*>(smem + sa_a) = a0;

            int stage = 0;
            for (int gc = 0; gc < 256; gc++) {
                if (gc <= 254) { CP_WAIT(1); } else { CP_WAIT(0); }
                __syncthreads();

                if (gc <= 254) {
                    int s1 = stage + 1; if (s1 == NSTAGE) s1 = 0;
                    *reinterpret_cast<uint4*>(smem + (size_t)s1 * BUFSZ + sa_a) = apend;
                }
                if (gc <= 253) {
                    apend = *reinterpret_cast<const uint4*>(a_addr(gc + 2));
                    int ns = stage + 2; if (ns >= NSTAGE) ns -= NSTAGE;
                    issue_b(gc + 2, ns);
                }

                {
                    const uint32_t abuf = Abase + (uint32_t)stage * BUFSZ;
                    const uint32_t bbuf = Bbase + (uint32_t)stage * BUFSZ;
#pragma unroll
                    for (int ks = 0; ks < 2; ks++) {
                        uint32_t Bh[2][4];
#pragma unroll
                        for (int jj = 0; jj < 2; jj++)
                            ldsm4(Bh[jj], bbuf + jj * (16 * PITCH) + ks * 32);
                        uint32_t Ah[2][4];
#pragma unroll
                        for (int mt = 0; mt < 2; mt++)
                            ldsm4(Ah[mt], abuf + mt * (16 * PITCH) + ks * 32);
#pragma unroll
                        for (int mt = 0; mt < 2; mt++)
#pragma unroll
                            for (int jj = 0; jj < 2; jj++)
#pragma unroll
                                for (int h = 0; h < 2; h++)
                                    mma_f16(d[mt][jj * 2 + h], Ah[mt], Bh[jj][h], Bh[jj][2 + h]);
                    }
                }

                if ((gc & 31) == 31) {
                    const int o0 = (gc >> 5) * 128;
                    const int cb = o0 + wx * 32 + (lane & 3) * 2;
#pragma unroll
                    for (int mt = 0; mt < 2; mt++) {
#pragma unroll
                        for (int j = 0; j < 4; j++) {
                            const int o = cb + j * 8;
                            const float w0 = wss[o], w1 = wss[o + 1];
                            const float q0 = qbs[o], q1 = qbs[o + 1];
                            part[mt * 2 + 0] += w0 * ftanh(d[mt][j][0] + q0) + w1 * ftanh(d[mt][j][1] + q1);
                            part[mt * 2 + 1] += w0 * ftanh(d[mt][j][2] + q0) + w1 * ftanh(d[mt][j][3] + q1);
                            d[mt][j][0] = 0.0f; d[mt][j][1] = 0.0f;
                            d[mt][j][2] = 0.0f; d[mt][j][3] = 0.0f;
                        }
                    }
                }
                if (++stage == NSTAGE) stage = 0;
            }

#pragma unroll
            for (int i = 0; i < 4; i++) {
                part[i] += __shfl_xor_sync(0xffffffffu, part[i], 1);
                part[i] += __shfl_xor_sync(0xffffffffu, part[i], 2);
            }
            float* rd = reinterpret_cast<float*>(smem + SM_RED);
            if ((lane & 3) == 0) {
                const int r0 = wy * 32 + (lane >> 2);
#pragma unroll
                for (int mt = 0; mt < 2; mt++) {
                    rd[wx * 64 + r0 + mt * 16]     = part[mt * 2 + 0];
                    rd[wx * 64 + r0 + mt * 16 + 8] = part[mt * 2 + 1];
                }
            }
            __syncthreads();
            if (tid < 64) {
                const float s = rd[tid] + rd[64 + tid] + rd[128 + tid] + rd[192 + tid];
                g_score[b * VLEN + v0 + tid] = s;
            }
            __threadfence();
            __syncthreads();
            if (tid == 0) atomicAdd(&g_done_score[b], 1);

        } else if (js < J_CTX) {
            // ================= softmax for batch b =================
            const int b = js - J_SOFT;
            if (tid == 0) {
                while (atomicAdd(&g_done_score[b], 0) < 64) __nanosleep(200);
            }
            __syncthreads();
            __threadfence();

            const float* s = g_score + b * VLEN;
            float local[16];
            float mx = -1e30f;
#pragma unroll
            for (int i = 0; i < 16; i++) {
                local[i] = s[tid + i * 256];
                mx = fmaxf(mx, local[i]);
            }
            red[tid] = mx;
            __syncthreads();
            for (int o = 128; o; o >>= 1) {
                if (tid < o) red[tid] = fmaxf(red[tid], red[tid + o]);
                __syncthreads();
            }
            mx = red[0];
            __syncthreads();
            float sum = 0.0f;
#pragma unroll
            for (int i = 0; i < 16; i++) {
                local[i] = expf(local[i] - mx);
                sum += local[i];
            }
            red[tid] = sum;
            __syncthreads();
            for (int o = 128; o; o >>= 1) {
                if (tid < o) red[tid] += red[tid + o];
                __syncthreads();
            }
            const float inv = 1.0f / red[0];
#pragma unroll
            for (int i = 0; i < 16; i++) attn_out[b * VLEN + tid + i * 256] = local[i] * inv;

            __threadfence();
            __syncthreads();
            if (tid == 0) atomicExch(&g_soft_flag[b], 1);

        } else if (js < J_RED) {
            // ================= context partial (b, vs) =================
            const int k  = js - J_CTX;
            const int b  = k >> 4;
            const int vs = k & 15;
            if (tid == 0) {
                while (atomicAdd(&g_soft_flag[b], 0) == 0) __nanosleep(200);
            }
            __syncthreads();
            __threadfence();

            float* a_s = reinterpret_cast<float*>(smem);
            const int v0 = vs * 256;
            a_s[tid] = attn_out[b * VLEN + v0 + tid];
            __syncthreads();

            const int h = tid * 4;
            const float* vp = value + ((size_t)b * VLEN + v0) * HDIM + h;
            float ax = 0.f, ay = 0.f, az = 0.f, aw = 0.f;
            for (int v = 0; v < 256; v += 8) {
#pragma unroll
                for (int j = 0; j < 8; j++) {
                    const float4 x = *reinterpret_cast<const float4*>(vp + (size_t)(v + j) * HDIM);
                    const float a = a_s[v + j];
                    ax += a * x.x; ay += a * x.y; az += a * x.z; aw += a * x.w;
                }
            }
            *reinterpret_cast<float4*>(g_ctx_part + ((size_t)vs * BATCH + b) * HDIM + h) =
                make_float4(ax, ay, az, aw);
            __threadfence();
            __syncthreads();
            if (tid == 0) atomicAdd(&g_ctx_done[b], 1);

        } else {
            // ================= context reduce for batch b =================
            const int b = js - J_RED;
            if (tid == 0) {
                while (atomicAdd(&g_ctx_done[b], 0) < 16) __nanosleep(200);
            }
            __syncthreads();
            __threadfence();
#pragma unroll
            for (int r = 0; r < 4; r++) {
                const int h = tid + r * 256;
                float s = 0.0f;
#pragma unroll
                for (int vs = 0; vs < 16; vs++)
                    s += g_ctx_part[(size_t)vs * BATCH * HDIM + b * HDIM + h];
                ctx_out[b * HDIM + h] = s;
            }
        }
    }
}

// ---------------------------------------------------------------------------
// Launch. Inputs: query, key, value, Wq, Wk, bias, Ws, bs.
// Output: context (32*1024) then attn (32*4096).
// ---------------------------------------------------------------------------
extern "C" void kernel_launch(void* const* d_in, const int* in_sizes, int n_in,
                              void* d_out, int out_size) {
    const float* query = (const float*)d_in[0];
    const float* key   = (const float*)d_in[1];
    const float* value = (const float*)d_in[2];
    const float* Wq    = (const float*)d_in[3];
    const float* Wk    = (const float*)d_in[4];
    const float* bias  = (const float*)d_in[5];
    const float* Ws    = (const float*)d_in[6];

    float* out  = (float*)d_out;
    float* ctx  = out;                    // (B, 1, H)
    float* attn = out + BATCH * HDIM;     // (B, V)

    cudaFuncSetAttribute(fused_kernel, cudaFuncAttributeMaxDynamicSharedMemorySize, SM_TOTAL);

    init_kernel<<<1, 256>>>();
    fused_kernel<<<GRID_P, 256, SM_TOTAL>>>(key, Ws, value, query, Wq, bias, Wk, attn, ctx);
}